// round 5
// baseline (speedup 1.0000x reference)
#include <cuda_runtime.h>

// GATv3Psi: N=100000, E=3200000, edge_attr [E,16]
// d_out: [ out(N) | attn(E) | pair_pred(2E) ]; edge_index int32.
// Shift-free softmax; pass-1 float2 RED accumulates {denom, num}; pass 2 atomic-free.

#define MAX_N 100000
#define MAX_E 3200000

__device__ float  g_ex[MAX_E];     // exp(score) per edge
__device__ float2 g_nd[MAX_N];     // {denom, num} accumulators
__device__ float  g_rinv[MAX_N];   // 1/(denom+eps)

// ---------------- Pass 1: 2 edges/thread, grid-stride ----------------
__global__ void k_edge1(const float* __restrict__ x,
                        const int* __restrict__ ei,         // [2,E] int32
                        const float* __restrict__ ea,       // [E,16]
                        const float* __restrict__ W,        // [1,1]
                        const float* __restrict__ Wn,       // [2,2]
                        const float* __restrict__ We,       // [16,2]
                        float* __restrict__ pair,           // [E,2]
                        int E) {
    float w00  = W[0];
    float wn00 = Wn[0], wn01 = Wn[1], wn10 = Wn[2], wn11 = Wn[3];
    float we0[16], we1[16];
    #pragma unroll
    for (int k = 0; k < 16; k++) { we0[k] = We[2*k]; we1[k] = We[2*k + 1]; }

    int Eh = E >> 1;                               // pairs of edges
    int stride = gridDim.x * blockDim.x;
    for (int t = blockIdx.x * blockDim.x + threadIdx.x; t < Eh; t += stride) {
        int e = t << 1;
        // batched index + gather loads (MLP)
        int2 s2 = *(const int2*)(ei + e);
        int2 d2 = *(const int2*)(ei + E + e);
        float xs0 = __ldg(&x[s2.x]);
        float xs1 = __ldg(&x[s2.y]);
        float xd0 = __ldg(&x[d2.x]);
        float xd1 = __ldg(&x[d2.y]);

        const float4* eav = (const float4*)(ea + (size_t)e * 16);
        float p00 = xs0 * wn00 + xd0 * wn10;
        float p01 = xs0 * wn01 + xd0 * wn11;
        float p10 = xs1 * wn00 + xd1 * wn10;
        float p11 = xs1 * wn01 + xd1 * wn11;
        #pragma unroll
        for (int j = 0; j < 4; j++) {
            float4 v = eav[j];
            p00 = fmaf(v.x, we0[4*j+0], fmaf(v.y, we0[4*j+1],
                  fmaf(v.z, we0[4*j+2], fmaf(v.w, we0[4*j+3], p00))));
            p01 = fmaf(v.x, we1[4*j+0], fmaf(v.y, we1[4*j+1],
                  fmaf(v.z, we1[4*j+2], fmaf(v.w, we1[4*j+3], p01))));
        }
        #pragma unroll
        for (int j = 0; j < 4; j++) {
            float4 v = eav[4 + j];
            p10 = fmaf(v.x, we0[4*j+0], fmaf(v.y, we0[4*j+1],
                  fmaf(v.z, we0[4*j+2], fmaf(v.w, we0[4*j+3], p10))));
            p11 = fmaf(v.x, we1[4*j+0], fmaf(v.y, we1[4*j+1],
                  fmaf(v.z, we1[4*j+2], fmaf(v.w, we1[4*j+3], p11))));
        }
        float a0 = (p00 >= 0.0f) ? p00 : 0.2f * p00;
        float b0 = (p01 >= 0.0f) ? p01 : 0.2f * p01;
        float a1 = (p10 >= 0.0f) ? p10 : 0.2f * p10;
        float b1 = (p11 >= 0.0f) ? p11 : 0.2f * p11;

        *(float4*)(pair + 2 * e) = make_float4(a0, b0, a1, b1);

        float ex0 = __expf(a0 - b0);
        float ex1 = __expf(a1 - b1);
        *(float2*)(g_ex + e) = make_float2(ex0, ex1);

        atomicAdd(&g_nd[d2.x], make_float2(ex0, ex0 * (xs0 * w00)));
        atomicAdd(&g_nd[d2.y], make_float2(ex1, ex1 * (xs1 * w00)));
    }
    // tail (E odd): handled by thread 0
    if ((E & 1) && blockIdx.x == 0 && threadIdx.x == 0) {
        int e = E - 1;
        int s = ei[e], d = ei[E + e];
        float xs = x[s], xd = x[d];
        float p0 = xs * wn00 + xd * wn10;
        float p1 = xs * wn01 + xd * wn11;
        const float* eav = ea + (size_t)e * 16;
        #pragma unroll
        for (int k = 0; k < 16; k++) {
            p0 = fmaf(eav[k], we0[k], p0);
            p1 = fmaf(eav[k], we1[k], p1);
        }
        float p0l = (p0 >= 0.0f) ? p0 : 0.2f * p0;
        float p1l = (p1 >= 0.0f) ? p1 : 0.2f * p1;
        pair[2*e] = p0l; pair[2*e+1] = p1l;
        float ex = __expf(p0l - p1l);
        g_ex[e] = ex;
        atomicAdd(&g_nd[d], make_float2(ex, ex * (xs * w00)));
    }
}

// ---------------- Finalize per node ----------------
__global__ void k_final(float* __restrict__ out, int n) {
    int i = blockIdx.x * blockDim.x + threadIdx.x;
    if (i < n) {
        float2 nd = g_nd[i];
        float r = 1.0f / (nd.x + 1e-16f);
        g_rinv[i] = r;
        out[i] = nd.y * r;
    }
}

// ---------------- Pass 2: 4 edges/thread, no atomics ----------------
__global__ void k_edge2(const int* __restrict__ ei,
                        float* __restrict__ attn, int E) {
    int t = blockIdx.x * blockDim.x + threadIdx.x;
    int e = t << 2;
    if (e + 3 < E) {
        int4   d4 = *(const int4*)(ei + E + e);
        float4 x4 = *(const float4*)(g_ex + e);
        float4 a4 = make_float4(x4.x * g_rinv[d4.x], x4.y * g_rinv[d4.y],
                                x4.z * g_rinv[d4.z], x4.w * g_rinv[d4.w]);
        *(float4*)(attn + e) = a4;
    } else {
        for (; e < E; e++) attn[e] = g_ex[e] * g_rinv[ei[E + e]];
    }
}

extern "C" void kernel_launch(void* const* d_in, const int* in_sizes, int n_in,
                              void* d_out, int out_size) {
    const float* x  = (const float*)d_in[0];
    const int*   ei = (const int*)d_in[1];
    const float* ea = (const float*)d_in[2];
    const float* W  = (const float*)d_in[3];
    const float* Wn = (const float*)d_in[4];
    const float* We = (const float*)d_in[5];

    int N = in_sizes[0];           // x is [N,1]
    int E = in_sizes[1] / 2;       // edge_index is [2,E]

    float* out  = (float*)d_out;   // [N]
    float* attn = out + N;         // [E]
    float* pair = attn + E;        // [E,2]

    // zero the {denom,num} accumulators (capturable async memset, no kernel)
    void* nd_ptr = nullptr;
    cudaGetSymbolAddress(&nd_ptr, g_nd);
    cudaMemsetAsync(nd_ptr, 0, (size_t)N * sizeof(float2));

    int pairs = E >> 1;
    int gb1 = (pairs + 255) / 256;
    if (gb1 > 2368) gb1 = 2368;                  // grid-stride, weights amortized
    k_edge1<<<gb1, 256>>>(x, ei, ea, W, Wn, We, pair, E);

    int nb = (N + 255) / 256;
    k_final<<<nb, 256>>>(out, N);

    int eb2 = ((E + 3) / 4 + 255) / 256;
    k_edge2<<<eb2, 256>>>(ei, attn, E);
}

// round 9
// speedup vs baseline: 1.0517x; 1.0517x over previous
#include <cuda_runtime.h>

// GATv3Psi: N=100000, E=3200000, edge_attr [E,16]
// d_out: [ out(N) | attn(E) | pair_pred(2E) ]; edge_index int32.
// Shift-free softmax; pass-1 float2 RED accumulates {denom, num}; pass 2 atomic-free.

#define MAX_N 100000
#define MAX_E 3200000

__device__ float  g_ex[MAX_E];     // exp(score) per edge
__device__ float2 g_nd[MAX_N];     // {denom, num} accumulators
__device__ float  g_rinv[MAX_N];   // 1/(denom+eps)

// ---------------- Pass 1: 1 edge/thread, grid-stride, occupancy-capped ----------------
__global__ void __launch_bounds__(256, 6)
k_edge1(const float* __restrict__ x,
        const int* __restrict__ ei,         // [2,E] int32
        const float* __restrict__ ea,       // [E,16]
        const float* __restrict__ W,        // [1,1]
        const float* __restrict__ Wn,       // [2,2]
        const float* __restrict__ We,       // [16,2]
        float* __restrict__ pair,           // [E,2]
        int E) {
    float w00  = W[0];
    float wn00 = Wn[0], wn01 = Wn[1], wn10 = Wn[2], wn11 = Wn[3];
    float we0[16], we1[16];
    #pragma unroll
    for (int k = 0; k < 16; k++) { we0[k] = We[2*k]; we1[k] = We[2*k + 1]; }

    int stride = gridDim.x * blockDim.x;
    for (int e = blockIdx.x * blockDim.x + threadIdx.x; e < E; e += stride) {
        int s = ei[e];
        int d = ei[E + e];
        float xs = __ldg(&x[s]);   // x: 400KB, L2-resident
        float xd = __ldg(&x[d]);

        const float4* eav = (const float4*)(ea + (size_t)e * 16);
        float p0 = xs * wn00 + xd * wn10;
        float p1 = xs * wn01 + xd * wn11;
        #pragma unroll
        for (int j = 0; j < 4; j++) {
            float4 v = eav[j];
            p0 = fmaf(v.x, we0[4*j+0], fmaf(v.y, we0[4*j+1],
                 fmaf(v.z, we0[4*j+2], fmaf(v.w, we0[4*j+3], p0))));
            p1 = fmaf(v.x, we1[4*j+0], fmaf(v.y, we1[4*j+1],
                 fmaf(v.z, we1[4*j+2], fmaf(v.w, we1[4*j+3], p1))));
        }
        float p0l = (p0 >= 0.0f) ? p0 : 0.2f * p0;   // leaky_relu(., 0.2)
        float p1l = (p1 >= 0.0f) ? p1 : 0.2f * p1;

        ((float2*)pair)[e] = make_float2(p0l, p1l);

        float ex = __expf(p0l - p1l);
        g_ex[e] = ex;
        atomicAdd(&g_nd[d], make_float2(ex, ex * (xs * w00)));
    }
}

// ---------------- Finalize per node ----------------
__global__ void k_final(float* __restrict__ out, int n) {
    int i = blockIdx.x * blockDim.x + threadIdx.x;
    if (i < n) {
        float2 nd = g_nd[i];
        float r = 1.0f / (nd.x + 1e-16f);
        g_rinv[i] = r;
        out[i] = nd.y * r;
    }
}

// ---------------- Pass 2: 4 edges/thread, no atomics ----------------
__global__ void k_edge2(const int* __restrict__ ei,
                        float* __restrict__ attn, int E) {
    int t = blockIdx.x * blockDim.x + threadIdx.x;
    int e = t << 2;
    if (e + 3 < E) {
        int4   d4 = *(const int4*)(ei + E + e);
        float4 x4 = *(const float4*)(g_ex + e);
        float4 a4 = make_float4(x4.x * g_rinv[d4.x], x4.y * g_rinv[d4.y],
                                x4.z * g_rinv[d4.z], x4.w * g_rinv[d4.w]);
        *(float4*)(attn + e) = a4;
    } else {
        for (; e < E; e++) attn[e] = g_ex[e] * g_rinv[ei[E + e]];
    }
}

extern "C" void kernel_launch(void* const* d_in, const int* in_sizes, int n_in,
                              void* d_out, int out_size) {
    const float* x  = (const float*)d_in[0];
    const int*   ei = (const int*)d_in[1];
    const float* ea = (const float*)d_in[2];
    const float* W  = (const float*)d_in[3];
    const float* Wn = (const float*)d_in[4];
    const float* We = (const float*)d_in[5];

    int N = in_sizes[0];           // x is [N,1]
    int E = in_sizes[1] / 2;       // edge_index is [2,E]

    float* out  = (float*)d_out;   // [N]
    float* attn = out + N;         // [E]
    float* pair = attn + E;        // [E,2]

    // zero the {denom,num} accumulators (capturable async memset, no kernel)
    void* nd_ptr = nullptr;
    cudaGetSymbolAddress(&nd_ptr, g_nd);
    cudaMemsetAsync(nd_ptr, 0, (size_t)N * sizeof(float2));

    int eb  = (E + 255) / 256;
    int gb1 = eb < 2368 ? eb : 2368;             // grid-stride, weights amortized
    k_edge1<<<gb1, 256>>>(x, ei, ea, W, Wn, We, pair, E);

    int nb = (N + 255) / 256;
    k_final<<<nb, 256>>>(out, N);

    int eb2 = ((E + 3) / 4 + 255) / 256;
    k_edge2<<<eb2, 256>>>(ei, attn, E);
}